// round 1
// baseline (speedup 1.0000x reference)
#include <cuda_runtime.h>

// EffectiveProbability: post = normalize(p * (CM @ c)) per pixel.
// Input normalizations cancel against the output normalization (scalar per row),
// so they are skipped.
//
// Shapes: prior/current [B=8, C=21, H=512, W=512] f32, cm [21,21] f32,
// out [B*H*W, 21] f32.

#define NCLS 21
#define HWSZ (512 * 512)
#define BLOCK 256

__global__ __launch_bounds__(BLOCK)
void eff_prob_kernel(const float* __restrict__ prior,
                     const float* __restrict__ current,
                     const float* __restrict__ cm,
                     float* __restrict__ out,
                     int npix)
{
    __shared__ float s_cm[NCLS * NCLS];
    __shared__ float s_out[BLOCK * NCLS];

    const int tid = threadIdx.x;

    // Stage confusion matrix once per block (broadcast reads later).
    for (int i = tid; i < NCLS * NCLS; i += BLOCK) s_cm[i] = cm[i];
    __syncthreads();

    const int n = blockIdx.x * BLOCK + tid;
    if (n < npix) {
        // pixel n = b*H*W + hw ; channel c lives at b*C*HW + c*HW + hw
        const int  b    = n / HWSZ;
        const int  hw   = n - b * HWSZ;
        const long base = (long)b * NCLS * HWSZ + hw;

        float cv[NCLS];
        float pv[NCLS];
        // Front-batched coalesced loads: high MLP, warp-contiguous addresses.
        #pragma unroll
        for (int j = 0; j < NCLS; j++) cv[j] = current[base + (long)j * HWSZ];
        #pragma unroll
        for (int j = 0; j < NCLS; j++) pv[j] = prior[base + (long)j * HWSZ];

        float post[NCLS];
        float acc = 0.0f;
        #pragma unroll
        for (int i = 0; i < NCLS; i++) {
            float s = 0.0f;
            #pragma unroll
            for (int j = 0; j < NCLS; j++)
                s = fmaf(s_cm[i * NCLS + j], cv[j], s);
            const float t = pv[i] * s;
            post[i] = t;
            acc += t;
        }
        const float inv = 1.0f / acc;

        // Stage into smem for coalesced global store.
        // Write stride 21 words across the warp: gcd(21,32)=1 -> conflict-free.
        #pragma unroll
        for (int i = 0; i < NCLS; i++)
            s_out[tid * NCLS + i] = post[i] * inv;
    }
    __syncthreads();

    // Flush block tile [BLOCK, 21] linearly -> fully coalesced 128B stores.
    const long out_base = (long)blockIdx.x * BLOCK * NCLS;
    const int  valid    = min(BLOCK, npix - blockIdx.x * BLOCK);
    const int  count    = valid * NCLS;
    for (int i = tid; i < count; i += BLOCK)
        out[out_base + i] = s_out[i];
}

extern "C" void kernel_launch(void* const* d_in, const int* in_sizes, int n_in,
                              void* d_out, int out_size)
{
    const float* prior   = (const float*)d_in[0];
    const float* current = (const float*)d_in[1];
    const float* cm      = (const float*)d_in[2];
    float*       out     = (float*)d_out;

    const int npix = in_sizes[0] / NCLS;   // B*H*W
    const int grid = (npix + BLOCK - 1) / BLOCK;
    eff_prob_kernel<<<grid, BLOCK>>>(prior, current, cm, out, npix);
}